// round 1
// baseline (speedup 1.0000x reference)
#include <cuda_runtime.h>
#include <cuda_bf16.h>

// Problem constants (fixed by reference setup_inputs)
constexpr int LYR = 5;
constexpr int NN  = 50000;   // nodes
constexpr int EE  = 600000;  // edges
constexpr int DD  = 128;     // features
constexpr int GG  = 256;     // graphs
constexpr int OO  = 10;      // outputs
constexpr float BN_EPS = 1e-5f;

// Scratch (device globals; no allocation allowed)
__device__ float g_X[NN * DD];      // node features (updated per layer)
__device__ float g_H[NN * DD];      // intermediate after conv_w1 path
__device__ float g_AGGR[NN * DD];   // scatter-add accumulator
__device__ float g_POOL[(LYR + 1) * GG * DD];
__device__ float g_CNT[GG];

__device__ __forceinline__ void red_add_v4(float* addr, float a, float b, float c, float d) {
    asm volatile(
        "{ .reg .u64 p; cvta.to.global.u64 p, %0;\n\t"
        "red.global.add.v4.f32 [p], {%1, %2, %3, %4}; }"
        :: "l"(addr), "f"(a), "f"(b), "f"(c), "f"(d) : "memory");
}

// ---------------------------------------------------------------------------
// Zeroing kernels
// ---------------------------------------------------------------------------
__global__ void zero_pool_kernel() {
    int idx = blockIdx.x * blockDim.x + threadIdx.x;
    if (idx < (LYR + 1) * GG * DD) g_POOL[idx] = 0.f;
    if (idx < GG) g_CNT[idx] = 0.f;
}

__global__ void zero_aggr_kernel() {
    float4* p = reinterpret_cast<float4*>(g_AGGR);
    const int n4 = NN * DD / 4;
    for (int i = blockIdx.x * blockDim.x + threadIdx.x; i < n4; i += gridDim.x * blockDim.x)
        p[i] = make_float4(0.f, 0.f, 0.f, 0.f);
}

// ---------------------------------------------------------------------------
// Graph-size counts
// ---------------------------------------------------------------------------
__global__ void counts_kernel(const int* __restrict__ batch) {
    int n = blockIdx.x * blockDim.x + threadIdx.x;
    if (n < NN) atomicAdd(&g_CNT[batch[n]], 1.0f);
}

// ---------------------------------------------------------------------------
// Per-layer pooling: POOL[layer][batch[n]][:] += x[n][:]
// one warp per node-chunk: thread handles 4 dims via float4
// ---------------------------------------------------------------------------
__global__ void pool_kernel(const float* __restrict__ xext, const int* __restrict__ batch, int layer) {
    const float* xp = xext ? xext : g_X;
    int idx = blockIdx.x * blockDim.x + threadIdx.x;
    int n = idx >> 5;
    int lane = idx & 31;
    if (n >= NN) return;
    int g = batch[n];
    float4 v = *reinterpret_cast<const float4*>(&xp[n * DD + lane * 4]);
    red_add_v4(&g_POOL[(size_t)layer * GG * DD + g * DD + lane * 4], v.x, v.y, v.z, v.w);
}

// ---------------------------------------------------------------------------
// Message + scatter: AGGR[dst] += relu(x[src] + bond_embed(edge_attr))
// One warp per edge (128 dims = 32 lanes x float4). Bond table in smem.
// ---------------------------------------------------------------------------
__global__ void msg_kernel(const float* __restrict__ xext,
                           const int* __restrict__ ei,
                           const int* __restrict__ eattr,
                           const float* __restrict__ bemb_l) {
    __shared__ float bs[3 * 8 * DD];   // 12KB
    for (int j = threadIdx.x; j < 3 * 8 * DD; j += blockDim.x) bs[j] = bemb_l[j];
    __syncthreads();

    const float* xp = xext ? xext : g_X;
    const int lane = threadIdx.x & 31;
    const int sub = threadIdx.x >> 5;                // 0..7 warps per block
    const int warps_total = gridDim.x * (blockDim.x >> 5);

    for (int e = blockIdx.x * (blockDim.x >> 5) + sub; e < EE; e += warps_total) {
        int src = ei[e];
        int dst = ei[EE + e];
        int a0 = eattr[e * 3 + 0];
        int a1 = eattr[e * 3 + 1];
        int a2 = eattr[e * 3 + 2];
        float4 e0 = *reinterpret_cast<const float4*>(&bs[a0 * DD + lane * 4]);
        float4 e1 = *reinterpret_cast<const float4*>(&bs[8 * DD + a1 * DD + lane * 4]);
        float4 e2 = *reinterpret_cast<const float4*>(&bs[16 * DD + a2 * DD + lane * 4]);
        float4 xv = *reinterpret_cast<const float4*>(&xp[(size_t)src * DD + lane * 4]);
        float mx = fmaxf(xv.x + e0.x + e1.x + e2.x, 0.f);
        float my = fmaxf(xv.y + e0.y + e1.y + e2.y, 0.f);
        float mz = fmaxf(xv.z + e0.z + e1.z + e2.z, 0.f);
        float mw = fmaxf(xv.w + e0.w + e1.w + e2.w, 0.f);
        red_add_v4(&g_AGGR[(size_t)dst * DD + lane * 4], mx, my, mz, mw);
    }
}

// ---------------------------------------------------------------------------
// Fused GEMM: C = act_input @ W + bias, then BN(eval) + ReLU
// MODE 1: A = (x + AGGR), output -> g_H
// MODE 2: A = g_H,        output -> g_X
// Block: 128 rows x 128 cols (full width), 256 threads, 8x8 per thread,
// K chunked by 16 through shared memory.
// ---------------------------------------------------------------------------
template <int MODE>
__global__ void __launch_bounds__(256, 2)
gemm_kernel(const float* __restrict__ xext,
            const float* __restrict__ W,
            const float* __restrict__ bias,
            const float* __restrict__ gamma,
            const float* __restrict__ beta,
            const float* __restrict__ mean,
            const float* __restrict__ var) {
    __shared__ float As[16][132];
    __shared__ float Wc[16][132];

    const int tid = threadIdx.x;
    const int tx = tid & 15;           // col group
    const int ty = tid >> 4;           // row group
    const int m0 = blockIdx.x * 128;

    const float* Ain = (MODE == 1) ? (xext ? xext : g_X) : g_H;
    const float4* W4 = reinterpret_cast<const float4*>(W);

    float acc[8][8];
#pragma unroll
    for (int i = 0; i < 8; i++)
#pragma unroll
        for (int j = 0; j < 8; j++) acc[i][j] = 0.f;

    for (int kc = 0; kc < DD; kc += 16) {
        __syncthreads();
        // Load W chunk [16 x 128]: 512 float4, 2 per thread
#pragma unroll
        for (int p = 0; p < 2; p++) {
            int f = tid + p * 256;           // 0..511
            int r = f >> 5;                  // k row within chunk
            int c4 = f & 31;                 // float4 col
            float4 wv = W4[(kc + r) * 32 + c4];
            *reinterpret_cast<float4*>(&Wc[r][c4 * 4]) = wv;
        }
        // Load A chunk [128 rows x 16 k], store transposed As[k][m]
#pragma unroll
        for (int p = 0; p < 2; p++) {
            int f = tid + p * 256;           // 0..511
            int row = f >> 2;                // 0..127
            int c4 = f & 3;                  // k-group (4 k per float4)
            int m = m0 + row;
            float4 v = make_float4(0.f, 0.f, 0.f, 0.f);
            if (m < NN) {
                int gi = m * DD + kc + c4 * 4;
                v = *reinterpret_cast<const float4*>(&Ain[gi]);
                if (MODE == 1) {
                    float4 a2 = *reinterpret_cast<const float4*>(&g_AGGR[gi]);
                    v.x += a2.x; v.y += a2.y; v.z += a2.z; v.w += a2.w;
                }
            }
            As[c4 * 4 + 0][row] = v.x;
            As[c4 * 4 + 1][row] = v.y;
            As[c4 * 4 + 2][row] = v.z;
            As[c4 * 4 + 3][row] = v.w;
        }
        __syncthreads();

        float a_frag[8], b_frag[8];
#pragma unroll
        for (int kk = 0; kk < 16; kk++) {
            *reinterpret_cast<float4*>(&a_frag[0]) = *reinterpret_cast<float4*>(&As[kk][ty * 8]);
            *reinterpret_cast<float4*>(&a_frag[4]) = *reinterpret_cast<float4*>(&As[kk][ty * 8 + 4]);
            *reinterpret_cast<float4*>(&b_frag[0]) = *reinterpret_cast<float4*>(&Wc[kk][tx * 8]);
            *reinterpret_cast<float4*>(&b_frag[4]) = *reinterpret_cast<float4*>(&Wc[kk][tx * 8 + 4]);
#pragma unroll
            for (int i = 0; i < 8; i++)
#pragma unroll
                for (int j = 0; j < 8; j++)
                    acc[i][j] = fmaf(a_frag[i], b_frag[j], acc[i][j]);
        }
    }

    // Epilogue: y = relu((acc + bias)*scale + shift), scale=gamma*rsqrt(var+eps)
    const int ncol = tx * 8;
    float sc[8], sh[8];
#pragma unroll
    for (int j = 0; j < 8; j++) {
        float s = gamma[ncol + j] * rsqrtf(var[ncol + j] + BN_EPS);
        sc[j] = s;
        sh[j] = beta[ncol + j] + (bias[ncol + j] - mean[ncol + j]) * s;
    }
    float* Out = (MODE == 1) ? g_H : g_X;
#pragma unroll
    for (int i = 0; i < 8; i++) {
        int m = m0 + ty * 8 + i;
        if (m < NN) {
            float v[8];
#pragma unroll
            for (int j = 0; j < 8; j++)
                v[j] = fmaxf(fmaf(acc[i][j], sc[j], sh[j]), 0.f);
            *reinterpret_cast<float4*>(&Out[m * DD + ncol]) =
                make_float4(v[0], v[1], v[2], v[3]);
            *reinterpret_cast<float4*>(&Out[m * DD + ncol + 4]) =
                make_float4(v[4], v[5], v[6], v[7]);
        }
    }
}

// ---------------------------------------------------------------------------
// Head: out[g][o] = sum_i (POOL[i][g][:] / max(cnt,1)) @ fc_w[i] + fc_b[i]
// one block per graph, 128 threads (one per dim)
// ---------------------------------------------------------------------------
__global__ void head_kernel(const float* __restrict__ fcw,
                            const float* __restrict__ fcb,
                            float* __restrict__ out) {
    __shared__ float s[OO * DD];
    const int g = blockIdx.x;
    const int d = threadIdx.x;
    const float inv = 1.0f / fmaxf(g_CNT[g], 1.0f);

    float acc[OO];
#pragma unroll
    for (int o = 0; o < OO; o++) acc[o] = 0.f;

    for (int i = 0; i < LYR + 1; i++) {
        float p = g_POOL[(size_t)i * GG * DD + g * DD + d] * inv;
        const float* wrow = &fcw[((size_t)i * DD + d) * OO];
#pragma unroll
        for (int o = 0; o < OO; o++) acc[o] = fmaf(p, wrow[o], acc[o]);
    }
#pragma unroll
    for (int o = 0; o < OO; o++) s[o * DD + d] = acc[o];

    for (int st = 64; st > 0; st >>= 1) {
        __syncthreads();
        if (d < st) {
#pragma unroll
            for (int o = 0; o < OO; o++) s[o * DD + d] += s[o * DD + d + st];
        }
    }
    __syncthreads();
    if (d < OO) {
        float b = 0.f;
        for (int i = 0; i < LYR + 1; i++) b += fcb[i * OO + d];
        out[g * OO + d] = s[d * DD] + b;
    }
}

// ---------------------------------------------------------------------------
extern "C" void kernel_launch(void* const* d_in, const int* in_sizes, int n_in,
                              void* d_out, int out_size) {
    const float* x     = (const float*)d_in[0];
    const int*   ei    = (const int*)d_in[1];
    const int*   eattr = (const int*)d_in[2];
    const int*   batch = (const int*)d_in[3];
    const float* bemb  = (const float*)d_in[4];
    const float* w1    = (const float*)d_in[5];
    const float* b1    = (const float*)d_in[6];
    const float* cbg   = (const float*)d_in[7];
    const float* cbb   = (const float*)d_in[8];
    const float* cbm   = (const float*)d_in[9];
    const float* cbv   = (const float*)d_in[10];
    const float* w2    = (const float*)d_in[11];
    const float* b2    = (const float*)d_in[12];
    const float* bg    = (const float*)d_in[13];
    const float* bb    = (const float*)d_in[14];
    const float* bm    = (const float*)d_in[15];
    const float* bv    = (const float*)d_in[16];
    const float* fcw   = (const float*)d_in[17];
    const float* fcb   = (const float*)d_in[18];
    float* out = (float*)d_out;

    const int gemm_grid = (NN + 127) / 128;     // 391
    const int pool_grid = (NN * 32 + 255) / 256;

    zero_pool_kernel<<<((LYR + 1) * GG * DD + 255) / 256, 256>>>();
    counts_kernel<<<(NN + 255) / 256, 256>>>(batch);
    pool_kernel<<<pool_grid, 256>>>(x, batch, 0);

    for (int i = 0; i < LYR; i++) {
        const float* xin = (i == 0) ? x : nullptr;
        zero_aggr_kernel<<<2048, 256>>>();
        msg_kernel<<<2048, 256>>>(xin, ei, eattr, bemb + (size_t)i * 3 * 8 * DD);
        gemm_kernel<1><<<gemm_grid, 256>>>(xin, w1 + (size_t)i * DD * DD, b1 + i * DD,
                                           cbg + i * DD, cbb + i * DD, cbm + i * DD, cbv + i * DD);
        gemm_kernel<2><<<gemm_grid, 256>>>(nullptr, w2 + (size_t)i * DD * DD, b2 + i * DD,
                                           bg + i * DD, bb + i * DD, bm + i * DD, bv + i * DD);
        pool_kernel<<<pool_grid, 256>>>(nullptr, batch, i + 1);
    }
    head_kernel<<<GG, DD>>>(fcw, fcb, out);
}

// round 4
// speedup vs baseline: 1.1674x; 1.1674x over previous
#include <cuda_runtime.h>
#include <cuda_bf16.h>

constexpr int LYR = 5;
constexpr int NN  = 50000;
constexpr int EE  = 600000;
constexpr int DD  = 128;
constexpr int GG  = 256;
constexpr int OO  = 10;
constexpr float BN_EPS = 1e-5f;

__device__ float g_X[NN * DD];
__device__ float g_AGGR[NN * DD];
__device__ float g_POOL[(LYR + 1) * GG * DD];
__device__ float g_CNT[GG];

__device__ __forceinline__ void red_add_v4(float* addr, float a, float b, float c, float d) {
    asm volatile(
        "{ .reg .u64 p; cvta.to.global.u64 p, %0;\n\t"
        "red.global.add.v4.f32 [p], {%1, %2, %3, %4}; }"
        :: "l"(addr), "f"(a), "f"(b), "f"(c), "f"(d) : "memory");
}

// ---------------------------------------------------------------------------
__global__ void zero_pool_kernel() {
    int idx = blockIdx.x * blockDim.x + threadIdx.x;
    if (idx < (LYR + 1) * GG * DD) g_POOL[idx] = 0.f;
    if (idx < GG) g_CNT[idx] = 0.f;
}

__global__ void zero_aggr_kernel() {
    float4* p = reinterpret_cast<float4*>(g_AGGR);
    const int n4 = NN * DD / 4;
    for (int i = blockIdx.x * blockDim.x + threadIdx.x; i < n4; i += gridDim.x * blockDim.x)
        p[i] = make_float4(0.f, 0.f, 0.f, 0.f);
}

// ---------------------------------------------------------------------------
// Layer-0 pool (reads input x) + graph counts
// ---------------------------------------------------------------------------
__global__ void pool0_kernel(const float* __restrict__ x, const int* __restrict__ batch) {
    int idx = blockIdx.x * blockDim.x + threadIdx.x;
    int n = idx >> 5;
    int lane = idx & 31;
    if (n >= NN) return;
    int g = batch[n];
    if (lane == 0) atomicAdd(&g_CNT[g], 1.0f);
    float4 v = *reinterpret_cast<const float4*>(&x[n * DD + lane * 4]);
    red_add_v4(&g_POOL[g * DD + lane * 4], v.x, v.y, v.z, v.w);
}

// ---------------------------------------------------------------------------
// Message + scatter: AGGR[dst] += relu(x[src] + bond_embed(edge_attr))
// ---------------------------------------------------------------------------
__global__ void msg_kernel(const float* __restrict__ xext,
                           const int* __restrict__ ei,
                           const int* __restrict__ eattr,
                           const float* __restrict__ bemb_l) {
    __shared__ float bs[3 * 8 * DD];
    for (int j = threadIdx.x; j < 3 * 8 * DD; j += blockDim.x) bs[j] = bemb_l[j];
    __syncthreads();

    const float* xp = xext ? xext : g_X;
    const int lane = threadIdx.x & 31;
    const int sub = threadIdx.x >> 5;
    const int warps_total = gridDim.x * (blockDim.x >> 5);

    for (int e = blockIdx.x * (blockDim.x >> 5) + sub; e < EE; e += warps_total) {
        int src = ei[e];
        int dst = ei[EE + e];
        int a0 = eattr[e * 3 + 0];
        int a1 = eattr[e * 3 + 1];
        int a2 = eattr[e * 3 + 2];
        float4 e0 = *reinterpret_cast<const float4*>(&bs[a0 * DD + lane * 4]);
        float4 e1 = *reinterpret_cast<const float4*>(&bs[8 * DD + a1 * DD + lane * 4]);
        float4 e2 = *reinterpret_cast<const float4*>(&bs[16 * DD + a2 * DD + lane * 4]);
        float4 xv = *reinterpret_cast<const float4*>(&xp[(size_t)src * DD + lane * 4]);
        float mx = fmaxf(xv.x + e0.x + e1.x + e2.x, 0.f);
        float my = fmaxf(xv.y + e0.y + e1.y + e2.y, 0.f);
        float mz = fmaxf(xv.z + e0.z + e1.z + e2.z, 0.f);
        float mw = fmaxf(xv.w + e0.w + e1.w + e2.w, 0.f);
        red_add_v4(&g_AGGR[(size_t)dst * DD + lane * 4], mx, my, mz, mw);
    }
}

// ---------------------------------------------------------------------------
// Fused layer kernel:
//   A = x + AGGR (AGGR zeroed after read)
//   H1 = relu(bn1(A @ W1 + b1))        -> kept in shared memory
//   Xn = relu(bn2(H1 @ W2 + b2))       -> g_X  + pool atomics
// Block: 128 rows, 256 threads, 8x8 accum per thread, K chunked by 16.
// Dynamic smem: As[16][132] + Wc[16][132] + Hs[128][132]
// ---------------------------------------------------------------------------
__global__ void __launch_bounds__(256, 2)
fused_layer_kernel(const float* __restrict__ xext,
                   const int* __restrict__ batch,
                   const float* __restrict__ W1, const float* __restrict__ b1,
                   const float* __restrict__ g1, const float* __restrict__ be1,
                   const float* __restrict__ mu1, const float* __restrict__ v1,
                   const float* __restrict__ W2, const float* __restrict__ b2,
                   const float* __restrict__ g2, const float* __restrict__ be2,
                   const float* __restrict__ mu2, const float* __restrict__ v2,
                   int layer) {
    extern __shared__ float sm[];
    float* As = sm;                    // [16][132]
    float* Wc = sm + 16 * 132;         // [16][132]
    float* Hs = sm + 2 * 16 * 132;     // [128][132]

    const int tid = threadIdx.x;
    const int tx = tid & 15;
    const int ty = tid >> 4;
    const int m0 = blockIdx.x * 128;
    const int ncol = tx * 8;

    const float* Ain = xext ? xext : g_X;
    const float4* W1v = reinterpret_cast<const float4*>(W1);
    const float4* W2v = reinterpret_cast<const float4*>(W2);

    float acc[8][8];
#pragma unroll
    for (int i = 0; i < 8; i++)
#pragma unroll
        for (int j = 0; j < 8; j++) acc[i][j] = 0.f;

    // ---------------- Pass 1: A @ W1 ----------------
    for (int kc = 0; kc < DD; kc += 16) {
        __syncthreads();
#pragma unroll
        for (int p = 0; p < 2; p++) {
            int f = tid + p * 256;
            int r = f >> 5;
            int c4 = f & 31;
            float4 wv = W1v[(kc + r) * 32 + c4];
            *reinterpret_cast<float4*>(&Wc[r * 132 + c4 * 4]) = wv;
        }
#pragma unroll
        for (int p = 0; p < 2; p++) {
            int f = tid + p * 256;
            int row = f >> 2;
            int c4 = f & 3;
            int m = m0 + row;
            float4 v = make_float4(0.f, 0.f, 0.f, 0.f);
            if (m < NN) {
                int gi = m * DD + kc + c4 * 4;
                v = *reinterpret_cast<const float4*>(&Ain[gi]);
                float4 a2 = *reinterpret_cast<const float4*>(&g_AGGR[gi]);
                v.x += a2.x; v.y += a2.y; v.z += a2.z; v.w += a2.w;
                // reset AGGR for the next layer's message pass
                *reinterpret_cast<float4*>(&g_AGGR[gi]) = make_float4(0.f, 0.f, 0.f, 0.f);
            }
            As[(c4 * 4 + 0) * 132 + row] = v.x;
            As[(c4 * 4 + 1) * 132 + row] = v.y;
            As[(c4 * 4 + 2) * 132 + row] = v.z;
            As[(c4 * 4 + 3) * 132 + row] = v.w;
        }
        __syncthreads();

        float a_frag[8], b_frag[8];
#pragma unroll
        for (int kk = 0; kk < 16; kk++) {
            *reinterpret_cast<float4*>(&a_frag[0]) = *reinterpret_cast<float4*>(&As[kk * 132 + ty * 8]);
            *reinterpret_cast<float4*>(&a_frag[4]) = *reinterpret_cast<float4*>(&As[kk * 132 + ty * 8 + 4]);
            *reinterpret_cast<float4*>(&b_frag[0]) = *reinterpret_cast<float4*>(&Wc[kk * 132 + ncol]);
            *reinterpret_cast<float4*>(&b_frag[4]) = *reinterpret_cast<float4*>(&Wc[kk * 132 + ncol + 4]);
#pragma unroll
            for (int i = 0; i < 8; i++)
#pragma unroll
                for (int j = 0; j < 8; j++)
                    acc[i][j] = fmaf(a_frag[i], b_frag[j], acc[i][j]);
        }
    }

    // Epilogue 1: bn1 + relu, store transposed into Hs[k][m]
    {
        float sc[8], sh[8];
#pragma unroll
        for (int j = 0; j < 8; j++) {
            float s = g1[ncol + j] * rsqrtf(v1[ncol + j] + BN_EPS);
            sc[j] = s;
            sh[j] = be1[ncol + j] + (b1[ncol + j] - mu1[ncol + j]) * s;
        }
#pragma unroll
        for (int j = 0; j < 8; j++) {
            float r0 = fmaxf(fmaf(acc[0][j], sc[j], sh[j]), 0.f);
            float r1 = fmaxf(fmaf(acc[1][j], sc[j], sh[j]), 0.f);
            float r2 = fmaxf(fmaf(acc[2][j], sc[j], sh[j]), 0.f);
            float r3 = fmaxf(fmaf(acc[3][j], sc[j], sh[j]), 0.f);
            *reinterpret_cast<float4*>(&Hs[(ncol + j) * 132 + ty * 8]) = make_float4(r0, r1, r2, r3);
            float r4 = fmaxf(fmaf(acc[4][j], sc[j], sh[j]), 0.f);
            float r5 = fmaxf(fmaf(acc[5][j], sc[j], sh[j]), 0.f);
            float r6 = fmaxf(fmaf(acc[6][j], sc[j], sh[j]), 0.f);
            float r7 = fmaxf(fmaf(acc[7][j], sc[j], sh[j]), 0.f);
            *reinterpret_cast<float4*>(&Hs[(ncol + j) * 132 + ty * 8 + 4]) = make_float4(r4, r5, r6, r7);
        }
    }

    // ---------------- Pass 2: H1 @ W2 ----------------
#pragma unroll
    for (int i = 0; i < 8; i++)
#pragma unroll
        for (int j = 0; j < 8; j++) acc[i][j] = 0.f;

    for (int kc = 0; kc < DD; kc += 16) {
        __syncthreads();
#pragma unroll
        for (int p = 0; p < 2; p++) {
            int f = tid + p * 256;
            int r = f >> 5;
            int c4 = f & 31;
            float4 wv = W2v[(kc + r) * 32 + c4];
            *reinterpret_cast<float4*>(&Wc[r * 132 + c4 * 4]) = wv;
        }
        __syncthreads();

        float a_frag[8], b_frag[8];
#pragma unroll
        for (int kk = 0; kk < 16; kk++) {
            *reinterpret_cast<float4*>(&a_frag[0]) = *reinterpret_cast<float4*>(&Hs[(kc + kk) * 132 + ty * 8]);
            *reinterpret_cast<float4*>(&a_frag[4]) = *reinterpret_cast<float4*>(&Hs[(kc + kk) * 132 + ty * 8 + 4]);
            *reinterpret_cast<float4*>(&b_frag[0]) = *reinterpret_cast<float4*>(&Wc[kk * 132 + ncol]);
            *reinterpret_cast<float4*>(&b_frag[4]) = *reinterpret_cast<float4*>(&Wc[kk * 132 + ncol + 4]);
#pragma unroll
            for (int i = 0; i < 8; i++)
#pragma unroll
                for (int j = 0; j < 8; j++)
                    acc[i][j] = fmaf(a_frag[i], b_frag[j], acc[i][j]);
        }
    }

    // Epilogue 2: bn2 + relu -> g_X, plus pooled atomics
    {
        float sc[8], sh[8];
#pragma unroll
        for (int j = 0; j < 8; j++) {
            float s = g2[ncol + j] * rsqrtf(v2[ncol + j] + BN_EPS);
            sc[j] = s;
            sh[j] = be2[ncol + j] + (b2[ncol + j] - mu2[ncol + j]) * s;
        }
        float* poolbase = &g_POOL[(size_t)(layer + 1) * GG * DD];
#pragma unroll
        for (int i = 0; i < 8; i++) {
            int m = m0 + ty * 8 + i;
            if (m < NN) {
                float w[8];
#pragma unroll
                for (int j = 0; j < 8; j++)
                    w[j] = fmaxf(fmaf(acc[i][j], sc[j], sh[j]), 0.f);
                *reinterpret_cast<float4*>(&g_X[m * DD + ncol]) =
                    make_float4(w[0], w[1], w[2], w[3]);
                *reinterpret_cast<float4*>(&g_X[m * DD + ncol + 4]) =
                    make_float4(w[4], w[5], w[6], w[7]);
                int g = batch[m];
                red_add_v4(&poolbase[g * DD + ncol], w[0], w[1], w[2], w[3]);
                red_add_v4(&poolbase[g * DD + ncol + 4], w[4], w[5], w[6], w[7]);
            }
        }
    }
}

// ---------------------------------------------------------------------------
__global__ void head_kernel(const float* __restrict__ fcw,
                            const float* __restrict__ fcb,
                            float* __restrict__ out) {
    __shared__ float s[OO * DD];
    const int g = blockIdx.x;
    const int d = threadIdx.x;
    const float inv = 1.0f / fmaxf(g_CNT[g], 1.0f);

    float acc[OO];
#pragma unroll
    for (int o = 0; o < OO; o++) acc[o] = 0.f;

    for (int i = 0; i < LYR + 1; i++) {
        float p = g_POOL[(size_t)i * GG * DD + g * DD + d] * inv;
        const float* wrow = &fcw[((size_t)i * DD + d) * OO];
#pragma unroll
        for (int o = 0; o < OO; o++) acc[o] = fmaf(p, wrow[o], acc[o]);
    }
#pragma unroll
    for (int o = 0; o < OO; o++) s[o * DD + d] = acc[o];

    for (int st = 64; st > 0; st >>= 1) {
        __syncthreads();
        if (d < st) {
#pragma unroll
            for (int o = 0; o < OO; o++) s[o * DD + d] += s[o * DD + d + st];
        }
    }
    __syncthreads();
    if (d < OO) {
        float b = 0.f;
        for (int i = 0; i < LYR + 1; i++) b += fcb[i * OO + d];
        out[g * OO + d] = s[d * DD] + b;
    }
}

// ---------------------------------------------------------------------------
extern "C" void kernel_launch(void* const* d_in, const int* in_sizes, int n_in,
                              void* d_out, int out_size) {
    const float* x     = (const float*)d_in[0];
    const int*   ei    = (const int*)d_in[1];
    const int*   eattr = (const int*)d_in[2];
    const int*   batch = (const int*)d_in[3];
    const float* bemb  = (const float*)d_in[4];
    const float* w1    = (const float*)d_in[5];
    const float* b1    = (const float*)d_in[6];
    const float* cbg   = (const float*)d_in[7];
    const float* cbb   = (const float*)d_in[8];
    const float* cbm   = (const float*)d_in[9];
    const float* cbv   = (const float*)d_in[10];
    const float* w2    = (const float*)d_in[11];
    const float* b2    = (const float*)d_in[12];
    const float* bg    = (const float*)d_in[13];
    const float* bb    = (const float*)d_in[14];
    const float* bm    = (const float*)d_in[15];
    const float* bv    = (const float*)d_in[16];
    const float* fcw   = (const float*)d_in[17];
    const float* fcb   = (const float*)d_in[18];
    float* out = (float*)d_out;

    const int gemm_grid = (NN + 127) / 128;           // 391
    const int pool_grid = (NN * 32 + 255) / 256;
    const int SMEM_FUSED = (2 * 16 * 132 + 128 * 132) * 4;  // 84480 bytes

    static bool attr_set = false;
    if (!attr_set) {
        cudaFuncSetAttribute(fused_layer_kernel,
                             cudaFuncAttributeMaxDynamicSharedMemorySize, SMEM_FUSED);
        attr_set = true;
    }

    zero_pool_kernel<<<((LYR + 1) * GG * DD + 255) / 256, 256>>>();
    zero_aggr_kernel<<<1024, 256>>>();   // establish invariant; maintained by fused kernel
    pool0_kernel<<<pool_grid, 256>>>(x, batch);

    for (int i = 0; i < LYR; i++) {
        const float* xin = (i == 0) ? x : nullptr;
        msg_kernel<<<2048, 256>>>(xin, ei, eattr, bemb + (size_t)i * 3 * 8 * DD);
        fused_layer_kernel<<<gemm_grid, 256, SMEM_FUSED>>>(
            xin, batch,
            w1 + (size_t)i * DD * DD, b1 + i * DD, cbg + i * DD, cbb + i * DD, cbm + i * DD, cbv + i * DD,
            w2 + (size_t)i * DD * DD, b2 + i * DD, bg + i * DD, bb + i * DD, bm + i * DD, bv + i * DD,
            i);
    }
    head_kernel<<<GG, DD>>>(fcw, fcb, out);
}

// round 6
// speedup vs baseline: 1.3940x; 1.1941x over previous
#include <cuda_runtime.h>
#include <cuda_bf16.h>
#include <cstdint>

constexpr int LYR = 5;
constexpr int NN  = 50000;
constexpr int EE  = 600000;
constexpr int DD  = 128;
constexpr int GG  = 256;
constexpr int OO  = 10;
constexpr float BN_EPS = 1e-5f;

__device__ float g_X[NN * DD];
__device__ float g_AGGR[NN * DD];
__device__ float g_POOL[(LYR + 1) * GG * DD];
__device__ float g_CNT[GG];
__device__ float g_COMBO[LYR * 512 * DD];
__device__ int4  g_EDGE[EE];
// Pre-transposed, split, swizzled weights: [layer][w1/w2][hi/lo][n*128 + swizzled k]
__device__ __align__(16) __nv_bfloat16 g_WT[LYR][2][2][DD * DD];

// ---------------------------------------------------------------------------
// Helpers
// ---------------------------------------------------------------------------
__device__ __forceinline__ uint32_t smem_u32(const void* p) {
    uint32_t a;
    asm("{ .reg .u64 t; cvta.to.shared.u64 t, %1; cvt.u32.u64 %0, t; }" : "=r"(a) : "l"(p));
    return a;
}

__device__ __forceinline__ void red_add_v4(float* addr, float a, float b, float c, float d) {
    asm volatile(
        "{ .reg .u64 p; cvta.to.global.u64 p, %0;\n\t"
        "red.global.add.v4.f32 [p], {%1, %2, %3, %4}; }"
        :: "l"(addr), "f"(a), "f"(b), "f"(c), "f"(d) : "memory");
}
__device__ __forceinline__ void red_add_v2(float* addr, float a, float b) {
    asm volatile(
        "{ .reg .u64 p; cvta.to.global.u64 p, %0;\n\t"
        "red.global.add.v2.f32 [p], {%1, %2}; }"
        :: "l"(addr), "f"(a), "f"(b) : "memory");
}

__device__ __forceinline__ void ldm_x4(uint32_t* r, uint32_t addr) {
    asm volatile("ldmatrix.sync.aligned.m8n8.x4.shared.b16 {%0,%1,%2,%3}, [%4];"
        : "=r"(r[0]), "=r"(r[1]), "=r"(r[2]), "=r"(r[3]) : "r"(addr));
}

#define MMA_BF16(d, a, b0_, b1_) \
    asm volatile("mma.sync.aligned.m16n8k16.row.col.f32.bf16.bf16.f32 " \
        "{%0,%1,%2,%3}, {%4,%5,%6,%7}, {%8,%9}, {%0,%1,%2,%3};" \
        : "+f"((d)[0]), "+f"((d)[1]), "+f"((d)[2]), "+f"((d)[3]) \
        : "r"((a)[0]), "r"((a)[1]), "r"((a)[2]), "r"((a)[3]), "r"(b0_), "r"(b1_))

__device__ __forceinline__ uint32_t pack_hi(float v0, float v1) {
    __nv_bfloat16 h0 = __float2bfloat16(v0), h1 = __float2bfloat16(v1);
    return (uint32_t)__bfloat16_as_ushort(h0) | ((uint32_t)__bfloat16_as_ushort(h1) << 16);
}
__device__ __forceinline__ uint32_t pack_lo(float v0, float v1) {
    __nv_bfloat16 h0 = __float2bfloat16(v0), h1 = __float2bfloat16(v1);
    __nv_bfloat16 l0 = __float2bfloat16(v0 - __bfloat162float(h0));
    __nv_bfloat16 l1 = __float2bfloat16(v1 - __bfloat162float(h1));
    return (uint32_t)__bfloat16_as_ushort(l0) | ((uint32_t)__bfloat16_as_ushort(l1) << 16);
}

// XOR-swizzled byte offset in a 128x128 bf16 tile (rows of 256B, 16B chunks)
__device__ __forceinline__ uint32_t sw_off(int row, int chunk) {
    return (uint32_t)(row * 256 + ((chunk ^ (row & 7)) << 4));
}

// SMEM layout (bytes)
constexpr int SM_SC1 = 0;
constexpr int SM_SH1 = 512;
constexpr int SM_SC2 = 1024;
constexpr int SM_SH2 = 1536;
constexpr int SM_AHI = 2048;                 // A tile (then H1) hi
constexpr int SM_ALO = SM_AHI + 32768;       // A/H1 lo
constexpr int SM_WHI = SM_ALO + 32768;       // W1 (then W2) hi
constexpr int SM_WLO = SM_WHI + 32768;       // W lo
constexpr int SM_TOTAL = SM_WLO + 32768;     // 133120 B

// ---------------------------------------------------------------------------
// Setup kernels
// ---------------------------------------------------------------------------
__global__ void zero_pool_kernel() {
    int idx = blockIdx.x * blockDim.x + threadIdx.x;
    if (idx < (LYR + 1) * GG * DD) g_POOL[idx] = 0.f;
    if (idx < GG) g_CNT[idx] = 0.f;
}

__global__ void zero_aggr_kernel() {
    float4* p = reinterpret_cast<float4*>(g_AGGR);
    const int n4 = NN * DD / 4;
    for (int i = blockIdx.x * blockDim.x + threadIdx.x; i < n4; i += gridDim.x * blockDim.x)
        p[i] = make_float4(0.f, 0.f, 0.f, 0.f);
}

__global__ void pool0_kernel(const float* __restrict__ x, const int* __restrict__ batch) {
    int idx = blockIdx.x * blockDim.x + threadIdx.x;
    int n = idx >> 5;
    int lane = idx & 31;
    if (n >= NN) return;
    int g = batch[n];
    if (lane == 0) atomicAdd(&g_CNT[g], 1.0f);
    float4 v = *reinterpret_cast<const float4*>(&x[n * DD + lane * 4]);
    red_add_v4(&g_POOL[g * DD + lane * 4], v.x, v.y, v.z, v.w);
}

__global__ void code_kernel(const int* __restrict__ ei, const int* __restrict__ eattr) {
    int e = blockIdx.x * blockDim.x + threadIdx.x;
    if (e < EE) {
        int4 v;
        v.x = ei[e];
        v.y = ei[EE + e];
        v.z = eattr[e * 3 + 0] + 8 * eattr[e * 3 + 1] + 64 * eattr[e * 3 + 2];
        v.w = 0;
        g_EDGE[e] = v;
    }
}

// All-layer combined bond tables: grid (512, LYR)
__global__ void combo_kernel(const float* __restrict__ bemb) {
    int c = blockIdx.x, l = blockIdx.y, d = threadIdx.x;
    const float* bl = bemb + (size_t)l * 3 * 8 * DD;
    int a0 = c & 7, a1 = (c >> 3) & 7, a2 = c >> 6;
    g_COMBO[((size_t)l * 512 + c) * DD + d] =
        bl[a0 * DD + d] + bl[(8 + a1) * DD + d] + bl[(16 + a2) * DD + d];
}

// Transpose + split + swizzle weights: grid (LYR, 2), 256 threads
__global__ void prep_w_kernel(const float* __restrict__ w1, const float* __restrict__ w2) {
    int l = blockIdx.x, which = blockIdx.y;
    const float* W = (which ? w2 : w1) + (size_t)l * DD * DD;
    __nv_bfloat16* dst_hi = g_WT[l][which][0];
    __nv_bfloat16* dst_lo = g_WT[l][which][1];
    for (int idx = threadIdx.x; idx < DD * DD; idx += blockDim.x) {
        int k = idx >> 7, n = idx & 127;          // coalesced read W[k][n]
        float v = W[idx];
        __nv_bfloat16 hi = __float2bfloat16(v);
        __nv_bfloat16 lo = __float2bfloat16(v - __bfloat162float(hi));
        int sidx = n * DD + (((k >> 3) ^ (n & 7)) << 3) + (k & 7);
        dst_hi[sidx] = hi;
        dst_lo[sidx] = lo;
    }
}

// ---------------------------------------------------------------------------
// Message + scatter: AGGR[dst] += relu(x[src] + combo[code])
// ---------------------------------------------------------------------------
__global__ void msg_kernel(const float* __restrict__ xext, int layer) {
    const float* xp = xext ? xext : g_X;
    const float* combo = g_COMBO + (size_t)layer * 512 * DD;
    const int lane = threadIdx.x & 31;
    const int sub = threadIdx.x >> 5;
    const int warps_total = gridDim.x * (blockDim.x >> 5);

    for (int e = blockIdx.x * (blockDim.x >> 5) + sub; e < EE; e += warps_total) {
        int4 ed = g_EDGE[e];
        float4 cv = *reinterpret_cast<const float4*>(&combo[(size_t)ed.z * DD + lane * 4]);
        float4 xv = *reinterpret_cast<const float4*>(&xp[(size_t)ed.x * DD + lane * 4]);
        float mx = fmaxf(xv.x + cv.x, 0.f);
        float my = fmaxf(xv.y + cv.y, 0.f);
        float mz = fmaxf(xv.z + cv.z, 0.f);
        float mw = fmaxf(xv.w + cv.w, 0.f);
        red_add_v4(&g_AGGR[(size_t)ed.y * DD + lane * 4], mx, my, mz, mw);
    }
}

// ---------------------------------------------------------------------------
// Fused layer kernel (HMMA bf16 split-3x):
//   A = x + AGGR (zeroing AGGR)  -> smem bf16 hi/lo (swizzled [M][K])
//   pass0: D1 = A @ W1^T; H1 = relu(bn1(D1)) -> smem (overwrites A); load W2
//   pass1: D2 = H1 @ W2^T; Xn = relu(bn2(D2)) -> g_X + pool atomics
// 8 warps; warp (wm=wid>>1, wn=wid&1): rows wm*32..+32, cols wn*64..+64
// per warp: 2 m-tiles x 8 n-tiles of m16n8k16, fp32 accum [64]
// ---------------------------------------------------------------------------
__global__ void __launch_bounds__(256)
fused_mma_kernel(const float* __restrict__ xext,
                 const int* __restrict__ batch,
                 const float* __restrict__ b1,
                 const float* __restrict__ g1, const float* __restrict__ be1,
                 const float* __restrict__ mu1, const float* __restrict__ v1,
                 const float* __restrict__ b2,
                 const float* __restrict__ g2, const float* __restrict__ be2,
                 const float* __restrict__ mu2, const float* __restrict__ v2,
                 int layer) {
    extern __shared__ char smc[];
    const int tid = threadIdx.x;
    const int lane = tid & 31;
    const int wid = tid >> 5;
    const int wm = wid >> 1;          // 0..3
    const int wn = wid & 1;           // 0..1
    const int m0 = blockIdx.x * 128;
    const float* Ain = xext ? xext : g_X;

    float* s_sc1 = reinterpret_cast<float*>(smc + SM_SC1);
    float* s_sh1 = reinterpret_cast<float*>(smc + SM_SH1);
    float* s_sc2 = reinterpret_cast<float*>(smc + SM_SC2);
    float* s_sh2 = reinterpret_cast<float*>(smc + SM_SH2);

    const uint32_t aHi = smem_u32(smc + SM_AHI);
    const uint32_t aLo = smem_u32(smc + SM_ALO);
    const uint32_t wHi = smem_u32(smc + SM_WHI);
    const uint32_t wLo = smem_u32(smc + SM_WLO);

    // ---- Phase 0: BN consts, A load+split, W1 copy ----
    if (tid < 128) {
        int c = tid;
        float s1 = g1[c] * rsqrtf(v1[c] + BN_EPS);
        s_sc1[c] = s1;
        s_sh1[c] = be1[c] + (b1[c] - mu1[c]) * s1;
        float s2 = g2[c] * rsqrtf(v2[c] + BN_EPS);
        s_sc2[c] = s2;
        s_sh2[c] = be2[c] + (b2[c] - mu2[c]) * s2;
    }
    {
        const int r = tid >> 1;        // local row 0..127
        const int h = tid & 1;         // col half
        const int m = m0 + r;
#pragma unroll
        for (int q = 0; q < 8; q++) {
            int c0 = h * 64 + q * 8;
            float4 v0 = make_float4(0.f, 0.f, 0.f, 0.f);
            float4 v1f = make_float4(0.f, 0.f, 0.f, 0.f);
            if (m < NN) {
                size_t gi = (size_t)m * DD + c0;
                v0 = *reinterpret_cast<const float4*>(&Ain[gi]);
                v1f = *reinterpret_cast<const float4*>(&Ain[gi + 4]);
                float4 a0 = *reinterpret_cast<const float4*>(&g_AGGR[gi]);
                float4 a1 = *reinterpret_cast<const float4*>(&g_AGGR[gi + 4]);
                v0.x += a0.x; v0.y += a0.y; v0.z += a0.z; v0.w += a0.w;
                v1f.x += a1.x; v1f.y += a1.y; v1f.z += a1.z; v1f.w += a1.w;
                *reinterpret_cast<float4*>(&g_AGGR[gi]) = make_float4(0.f, 0.f, 0.f, 0.f);
                *reinterpret_cast<float4*>(&g_AGGR[gi + 4]) = make_float4(0.f, 0.f, 0.f, 0.f);
            }
            uint32_t off = sw_off(r, h * 8 + q);
            uint4 hi4 = make_uint4(pack_hi(v0.x, v0.y), pack_hi(v0.z, v0.w),
                                   pack_hi(v1f.x, v1f.y), pack_hi(v1f.z, v1f.w));
            uint4 lo4 = make_uint4(pack_lo(v0.x, v0.y), pack_lo(v0.z, v0.w),
                                   pack_lo(v1f.x, v1f.y), pack_lo(v1f.z, v1f.w));
            *reinterpret_cast<uint4*>(smc + SM_AHI + off) = hi4;
            *reinterpret_cast<uint4*>(smc + SM_ALO + off) = lo4;
        }
    }
    {
        const uint4* sh = reinterpret_cast<const uint4*>(g_WT[layer][0][0]);
        const uint4* sl = reinterpret_cast<const uint4*>(g_WT[layer][0][1]);
        uint4* dh = reinterpret_cast<uint4*>(smc + SM_WHI);
        uint4* dl = reinterpret_cast<uint4*>(smc + SM_WLO);
#pragma unroll
        for (int i = 0; i < 8; i++) {
            dh[tid + i * 256] = sh[tid + i * 256];
            dl[tid + i * 256] = sl[tid + i * 256];
        }
    }
    __syncthreads();

    // per-lane ldmatrix addressing constants
    const int lrow = lane & 15;
    const int lhalf = lane >> 4;
    const int ar0 = wm * 32 + lrow;       // A rows, m-tile 0
    const int ar1 = ar0 + 16;             // m-tile 1
    const int ar0b = ar0 * 256, ar0x = ar0 & 7;
    const int ar1b = ar1 * 256, ar1x = ar1 & 7;
    int brb[4], brx[4];
#pragma unroll
    for (int p = 0; p < 4; p++) {
        int nr = wn * 64 + p * 16 + lrow;
        brb[p] = nr * 256;
        brx[p] = nr & 7;
    }

    float acc[64];
#pragma unroll
    for (int i = 0; i < 64; i++) acc[i] = 0.f;

    for (int pass = 0; pass < 2; ++pass) {
        // ---- term group 1: Ahi * (Whi + Wlo) ----
#pragma unroll
        for (int ks = 0; ks < 8; ks++) {
            const int ch = ks * 2 + lhalf;
            uint32_t a0[4], a1[4];
            ldm_x4(a0, aHi + ar0b + ((uint32_t)(ch ^ ar0x) << 4));
            ldm_x4(a1, aHi + ar1b + ((uint32_t)(ch ^ ar1x) << 4));
            uint32_t bh[4][4], bl[4][4];
#pragma unroll
            for (int p = 0; p < 4; p++) {
                uint32_t o = (uint32_t)(ch ^ brx[p]) << 4;
                ldm_x4(bh[p], wHi + brb[p] + o);
                ldm_x4(bl[p], wLo + brb[p] + o);
            }
#pragma unroll
            for (int p = 0; p < 4; p++) {
                MMA_BF16(acc + (2 * p) * 4,      a0, bh[p][0], bh[p][2]);
                MMA_BF16(acc + (2 * p + 1) * 4,  a0, bh[p][1], bh[p][3]);
                MMA_BF16(acc + 32 + (2 * p) * 4,     a1, bh[p][0], bh[p][2]);
                MMA_BF16(acc + 32 + (2 * p + 1) * 4, a1, bh[p][1], bh[p][3]);
                MMA_BF16(acc + (2 * p) * 4,      a0, bl[p][0], bl[p][2]);
                MMA_BF16(acc + (2 * p + 1) * 4,  a0, bl[p][1], bl[p][3]);
                MMA_BF16(acc + 32 + (2 * p) * 4,     a1, bl[p][0], bl[p][2]);
                MMA_BF16(acc + 32 + (2 * p + 1) * 4, a1, bl[p][1], bl[p][3]);
            }
        }
        // ---- term group 2: Alo * Whi ----
#pragma unroll
        for (int ks = 0; ks < 8; ks++) {
            const int ch = ks * 2 + lhalf;
            uint32_t a0[4], a1[4];
            ldm_x4(a0, aLo + ar0b + ((uint32_t)(ch ^ ar0x) << 4));
            ldm_x4(a1, aLo + ar1b + ((uint32_t)(ch ^ ar1x) << 4));
            uint32_t bh[4][4];
#pragma unroll
            for (int p = 0; p < 4; p++)
                ldm_x4(bh[p], wHi + brb[p] + ((uint32_t)(ch ^ brx[p]) << 4));
#pragma unroll
            for (int p = 0; p < 4; p++) {
                MMA_BF16(acc + (2 * p) * 4,      a0, bh[p][0], bh[p][2]);
                MMA_BF16(acc + (2 * p + 1) * 4,  a0, bh[p][1], bh[p][3]);
                MMA_BF16(acc + 32 + (2 * p) * 4,     a1, bh[p][0], bh[p][2]);
                MMA_BF16(acc + 32 + (2 * p + 1) * 4, a1, bh[p][1], bh[p][3]);
            }
        }
        __syncthreads();   // compute done; smem reusable

        if (pass == 0) {
            // Epilogue 1: H1 = relu(bn1(acc)) -> A bufs (hi/lo), zero acc
#pragma unroll
            for (int mt = 0; mt < 2; mt++) {
                int rbase = wm * 32 + mt * 16 + (lane >> 2);
#pragma unroll
                for (int h = 0; h < 2; h++) {
                    int rr = rbase + 8 * h;
                    int rb = rr * 256, rx = rr & 7;
#pragma unroll
                    for (int nt = 0; nt < 8; nt++) {
                        int c = wn * 64 + nt * 8 + 2 * (lane & 3);
                        int ai = mt * 32 + nt * 4 + 2 * h;
                        float v0 = fmaxf(fmaf(acc[ai],     s_sc1[c],     s_sh1[c]),     0.f);
                        float v1f = fmaxf(fmaf(acc[ai + 1], s_sc1[c + 1], s_sh1[c + 1]), 0.f);
                        uint32_t off = (uint32_t)(rb + (((c >> 3) ^ rx) << 4) + ((c & 7) << 1));
                        *reinterpret_cast<uint32_t*>(smc + SM_AHI + off) = pack_hi(v0, v1f);
                        *reinterpret_cast<uint32_t*>(smc + SM_ALO + off) = pack_lo(v0, v1f);
                    }
                }
            }
            // Load W2 into W bufs
            {
                const uint4* sh = reinterpret_cast<const uint4*>(g_WT[layer][1][0]);
                const uint4* sl = reinterpret_cast<const uint4*>(g_WT[layer][1][1]);
                uint4* dh = reinterpret_cast<uint4*>(smc + SM_WHI);
                uint4* dl = reinterpret_cast<uint4*>(smc + SM_WLO);
#pragma unroll
                for (int i = 0; i < 8; i++) {
                    dh[tid + i * 256] = sh[tid + i * 256];
                    dl[tid + i * 256] = sl[tid + i * 256];
                }
            }
#pragma unroll
            for (int i = 0; i < 64; i++) acc[i] = 0.f;
            __syncthreads();
        }
    }

    // ---- Epilogue 2: Xn = relu(bn2(acc)) -> g_X + pool atomics ----
    float* poolbase = &g_POOL[(size_t)(layer + 1) * GG * DD];
#pragma unroll
    for (int mt = 0; mt < 2; mt++) {
#pragma unroll
        for (int h = 0; h < 2; h++) {
            int m = m0 + wm * 32 + mt * 16 + (lane >> 2) + 8 * h;
            if (m < NN) {
                int g = batch[m];
#pragma unroll
                for (int nt = 0; nt < 8; nt++) {
                    int c = wn * 64 + nt * 8 + 2 * (lane & 3);
                    int ai = mt * 32 + nt * 4 + 2 * h;
                    float v0 = fmaxf(fmaf(acc[ai],     s_sc2[c],     s_sh2[c]),     0.f);
                    float v1f = fmaxf(fmaf(acc[ai + 1], s_sc2[c + 1], s_sh2[c + 1]), 0.f);
                    *reinterpret_cast<float2*>(&g_X[(size_t)m * DD + c]) = make_float2(v0, v1f);
                    red_add_v2(&poolbase[g * DD + c], v0, v1f);
                }
            }
        }
    }
}

// ---------------------------------------------------------------------------
__global__ void head_kernel(const float* __restrict__ fcw,
                            const float* __restrict__ fcb,
                            float* __restrict__ out) {
    __shared__ float s[OO * DD];
    const int g = blockIdx.x;
    const int d = threadIdx.x;
    const float inv = 1.0f / fmaxf(g_CNT[g], 1.0f);

    float acc[OO];
#pragma unroll
    for (int o = 0; o < OO; o++) acc[o] = 0.f;

    for (int i = 0; i < LYR + 1; i++) {
        float p = g_POOL[(size_t)i * GG * DD + g * DD + d] * inv;
        const float* wrow = &fcw[((size_t)i * DD + d) * OO];
#pragma unroll
        for (int o = 0; o < OO; o++) acc[o] = fmaf(p, wrow[o], acc[o]);
    }
#pragma unroll
    for (int o = 0; o < OO; o++) s[o * DD + d] = acc[o];

    for (int st = 64; st > 0; st >>= 1) {
        __syncthreads();
        if (d < st) {
#pragma unroll
            for (int o = 0; o < OO; o++) s[o * DD + d] += s[o * DD + d + st];
        }
    }
    __syncthreads();
    if (d < OO) {
        float b = 0.f;
        for (int i = 0; i < LYR + 1; i++) b += fcb[i * OO + d];
        out[g * OO + d] = s[d * DD] + b;
    }
}

// ---------------------------------------------------------------------------
extern "C" void kernel_launch(void* const* d_in, const int* in_sizes, int n_in,
                              void* d_out, int out_size) {
    const float* x     = (const float*)d_in[0];
    const int*   ei    = (const int*)d_in[1];
    const int*   eattr = (const int*)d_in[2];
    const int*   batch = (const int*)d_in[3];
    const float* bemb  = (const float*)d_in[4];
    const float* w1    = (const float*)d_in[5];
    const float* b1    = (const float*)d_in[6];
    const float* cbg   = (const float*)d_in[7];
    const float* cbb   = (const float*)d_in[8];
    const float* cbm   = (const float*)d_in[9];
    const float* cbv   = (const float*)d_in[10];
    const float* w2    = (const float*)d_in[11];
    const float* b2    = (const float*)d_in[12];
    const float* bg    = (const float*)d_in[13];
    const float* bb    = (const float*)d_in[14];
    const float* bm    = (const float*)d_in[15];
    const float* bv    = (const float*)d_in[16];
    const float* fcw   = (const float*)d_in[17];
    const float* fcb   = (const float*)d_in[18];
    float* out = (float*)d_out;

    const int gemm_grid = (NN + 127) / 128;           // 391
    const int pool_grid = (NN * 32 + 255) / 256;

    cudaFuncSetAttribute(fused_mma_kernel,
                         cudaFuncAttributeMaxDynamicSharedMemorySize, SM_TOTAL);

    zero_pool_kernel<<<((LYR + 1) * GG * DD + 255) / 256, 256>>>();
    zero_aggr_kernel<<<1024, 256>>>();   // invariant; maintained by fused kernel
    pool0_kernel<<<pool_grid, 256>>>(x, batch);
    code_kernel<<<(EE + 255) / 256, 256>>>(ei, eattr);
    combo_kernel<<<dim3(512, LYR), 128>>>(bemb);
    prep_w_kernel<<<dim3(LYR, 2), 256>>>(w1, w2);

    for (int i = 0; i < LYR; i++) {
        const float* xin = (i == 0) ? x : nullptr;
        msg_kernel<<<2048, 256>>>(xin, i);
        fused_mma_kernel<<<gemm_grid, 256, SM_TOTAL>>>(
            xin, batch,
            b1 + i * DD, cbg + i * DD, cbb + i * DD, cbm + i * DD, cbv + i * DD,
            b2 + i * DD, bg + i * DD, bb + i * DD, bm + i * DD, bv + i * DD,
            i);
    }
    head_kernel<<<GG, DD>>>(fcw, fcb, out);
}

// round 9
// speedup vs baseline: 1.6474x; 1.1817x over previous
#include <cuda_runtime.h>
#include <cuda_bf16.h>
#include <cstdint>

constexpr int LYR = 5;
constexpr int NN  = 50000;
constexpr int EE  = 600000;
constexpr int DD  = 128;
constexpr int GG  = 256;
constexpr int OO  = 10;
constexpr float BN_EPS = 1e-5f;

__device__ float g_X[NN * DD];
__device__ float g_AGGR[NN * DD];
__device__ float g_POOL[(LYR + 1) * GG * DD];
__device__ float g_CNT[GG];
__device__ float g_COMBO[LYR * 512 * DD];
// CSR (rebuilt every launch; edges sorted by dst)
__device__ int  g_DEG[NN];
__device__ int  g_ROWPTR[NN + 1];
__device__ int  g_WPOS[NN];
__device__ int2 g_ESRC[EE];          // {src, combo_code}
// Pre-transposed, split, swizzled weights: [layer][w1/w2][hi/lo][n*128 + swizzled k]
__device__ __align__(16) __nv_bfloat16 g_WT[LYR][2][2][DD * DD];

// ---------------------------------------------------------------------------
// Helpers
// ---------------------------------------------------------------------------
__device__ __forceinline__ uint32_t smem_u32(const void* p) {
    uint32_t a;
    asm("{ .reg .u64 t; cvta.to.shared.u64 t, %1; cvt.u32.u64 %0, t; }" : "=r"(a) : "l"(p));
    return a;
}

__device__ __forceinline__ void red_add_v4(float* addr, float a, float b, float c, float d) {
    asm volatile(
        "{ .reg .u64 p; cvta.to.global.u64 p, %0;\n\t"
        "red.global.add.v4.f32 [p], {%1, %2, %3, %4}; }"
        :: "l"(addr), "f"(a), "f"(b), "f"(c), "f"(d) : "memory");
}
__device__ __forceinline__ void red_add_v2(float* addr, float a, float b) {
    asm volatile(
        "{ .reg .u64 p; cvta.to.global.u64 p, %0;\n\t"
        "red.global.add.v2.f32 [p], {%1, %2}; }"
        :: "l"(addr), "f"(a), "f"(b) : "memory");
}

__device__ __forceinline__ void ldm_x4(uint32_t* r, uint32_t addr) {
    asm volatile("ldmatrix.sync.aligned.m8n8.x4.shared.b16 {%0,%1,%2,%3}, [%4];"
        : "=r"(r[0]), "=r"(r[1]), "=r"(r[2]), "=r"(r[3]) : "r"(addr));
}

#define MMA_BF16(d, a, b0_, b1_) \
    asm volatile("mma.sync.aligned.m16n8k16.row.col.f32.bf16.bf16.f32 " \
        "{%0,%1,%2,%3}, {%4,%5,%6,%7}, {%8,%9}, {%0,%1,%2,%3};" \
        : "+f"((d)[0]), "+f"((d)[1]), "+f"((d)[2]), "+f"((d)[3]) \
        : "r"((a)[0]), "r"((a)[1]), "r"((a)[2]), "r"((a)[3]), "r"(b0_), "r"(b1_))

__device__ __forceinline__ uint32_t pack_hi(float v0, float v1) {
    __nv_bfloat16 h0 = __float2bfloat16(v0), h1 = __float2bfloat16(v1);
    return (uint32_t)__bfloat16_as_ushort(h0) | ((uint32_t)__bfloat16_as_ushort(h1) << 16);
}
__device__ __forceinline__ uint32_t pack_lo(float v0, float v1) {
    __nv_bfloat16 h0 = __float2bfloat16(v0), h1 = __float2bfloat16(v1);
    __nv_bfloat16 l0 = __float2bfloat16(v0 - __bfloat162float(h0));
    __nv_bfloat16 l1 = __float2bfloat16(v1 - __bfloat162float(h1));
    return (uint32_t)__bfloat16_as_ushort(l0) | ((uint32_t)__bfloat16_as_ushort(l1) << 16);
}

// XOR-swizzled byte offset in a 128x128 bf16 tile (rows of 256B, 16B chunks)
__device__ __forceinline__ uint32_t sw_off(int row, int chunk) {
    return (uint32_t)(row * 256 + ((chunk ^ (row & 7)) << 4));
}

// SMEM layout (bytes)
constexpr int SM_SC1 = 0;
constexpr int SM_SH1 = 512;
constexpr int SM_SC2 = 1024;
constexpr int SM_SH2 = 1536;
constexpr int SM_AHI = 2048;
constexpr int SM_ALO = SM_AHI + 32768;
constexpr int SM_WHI = SM_ALO + 32768;
constexpr int SM_WLO = SM_WHI + 32768;
constexpr int SM_TOTAL = SM_WLO + 32768;     // 133120 B

// ---------------------------------------------------------------------------
// Setup kernels
// ---------------------------------------------------------------------------
__global__ void zero_pool_kernel() {
    int idx = blockIdx.x * blockDim.x + threadIdx.x;
    if (idx < (LYR + 1) * GG * DD) g_POOL[idx] = 0.f;
    if (idx < GG) g_CNT[idx] = 0.f;
    if (idx < NN) g_DEG[idx] = 0;
}

__global__ void pool0_kernel(const float* __restrict__ x, const int* __restrict__ batch) {
    int idx = blockIdx.x * blockDim.x + threadIdx.x;
    int n = idx >> 5;
    int lane = idx & 31;
    if (n >= NN) return;
    int g = batch[n];
    if (lane == 0) atomicAdd(&g_CNT[g], 1.0f);
    float4 v = *reinterpret_cast<const float4*>(&x[n * DD + lane * 4]);
    red_add_v4(&g_POOL[g * DD + lane * 4], v.x, v.y, v.z, v.w);
}

__global__ void hist_kernel(const int* __restrict__ ei) {
    int e = blockIdx.x * blockDim.x + threadIdx.x;
    if (e < EE) atomicAdd(&g_DEG[ei[EE + e]], 1);
}

// Single-block exclusive scan of g_DEG -> g_ROWPTR / g_WPOS
__global__ void scan_kernel() {
    __shared__ int part[1024];
    const int t = threadIdx.x;
    const int CH = (NN + 1023) / 1024;       // 49
    const int base = t * CH;
    int sum = 0;
    for (int j = 0; j < CH; j++) {
        int i = base + j;
        if (i < NN) sum += g_DEG[i];
    }
    part[t] = sum;
    __syncthreads();
    for (int off = 1; off < 1024; off <<= 1) {
        int v = (t >= off) ? part[t - off] : 0;
        __syncthreads();
        part[t] += v;
        __syncthreads();
    }
    int run = (t == 0) ? 0 : part[t - 1];
    for (int j = 0; j < CH; j++) {
        int i = base + j;
        if (i < NN) {
            g_ROWPTR[i] = run;
            g_WPOS[i] = run;
            run += g_DEG[i];
        }
    }
    if (t == 1023) g_ROWPTR[NN] = run;
}

__global__ void scatter_kernel(const int* __restrict__ ei, const int* __restrict__ eattr) {
    int e = blockIdx.x * blockDim.x + threadIdx.x;
    if (e < EE) {
        int dst = ei[EE + e];
        int pos = atomicAdd(&g_WPOS[dst], 1);
        int2 rec;
        rec.x = ei[e];
        rec.y = eattr[e * 3 + 0] + 8 * eattr[e * 3 + 1] + 64 * eattr[e * 3 + 2];
        g_ESRC[pos] = rec;
    }
}

// All-layer combined bond tables: grid (512, LYR)
__global__ void combo_kernel(const float* __restrict__ bemb) {
    int c = blockIdx.x, l = blockIdx.y, d = threadIdx.x;
    const float* bl = bemb + (size_t)l * 3 * 8 * DD;
    int a0 = c & 7, a1 = (c >> 3) & 7, a2 = c >> 6;
    g_COMBO[((size_t)l * 512 + c) * DD + d] =
        bl[a0 * DD + d] + bl[(8 + a1) * DD + d] + bl[(16 + a2) * DD + d];
}

// Transpose + split + swizzle weights: grid (LYR, 2), 256 threads
__global__ void prep_w_kernel(const float* __restrict__ w1, const float* __restrict__ w2) {
    int l = blockIdx.x, which = blockIdx.y;
    const float* W = (which ? w2 : w1) + (size_t)l * DD * DD;
    __nv_bfloat16* dst_hi = g_WT[l][which][0];
    __nv_bfloat16* dst_lo = g_WT[l][which][1];
    for (int idx = threadIdx.x; idx < DD * DD; idx += blockDim.x) {
        int k = idx >> 7, n = idx & 127;
        float v = W[idx];
        __nv_bfloat16 hi = __float2bfloat16(v);
        __nv_bfloat16 lo = __float2bfloat16(v - __bfloat162float(hi));
        int sidx = n * DD + (((k >> 3) ^ (n & 7)) << 3) + (k & 7);
        dst_hi[sidx] = hi;
        dst_lo[sidx] = lo;
    }
}

// ---------------------------------------------------------------------------
// CSR gather aggregation: AGGR[n] = sum over in-edges relu(x[src] + combo)
// One warp per node; register accumulation; plain store (no atomics).
// ---------------------------------------------------------------------------
__global__ void __launch_bounds__(256)
msg_csr_kernel(const float* __restrict__ xext, int layer) {
    const float* xp = xext ? xext : g_X;
    const float* combo = g_COMBO + (size_t)layer * 512 * DD;
    const int lane = threadIdx.x & 31;
    const int n = blockIdx.x * 8 + (threadIdx.x >> 5);
    if (n >= NN) return;

    const int s = g_ROWPTR[n];
    const int e = g_ROWPTR[n + 1];
    float4 acc = make_float4(0.f, 0.f, 0.f, 0.f);
#pragma unroll 2
    for (int i = s; i < e; i++) {
        int2 ed = g_ESRC[i];   // warp-uniform broadcast
        float4 cv = *reinterpret_cast<const float4*>(&combo[(size_t)ed.y * DD + lane * 4]);
        float4 xv = *reinterpret_cast<const float4*>(&xp[(size_t)ed.x * DD + lane * 4]);
        acc.x += fmaxf(xv.x + cv.x, 0.f);
        acc.y += fmaxf(xv.y + cv.y, 0.f);
        acc.z += fmaxf(xv.z + cv.z, 0.f);
        acc.w += fmaxf(xv.w + cv.w, 0.f);
    }
    *reinterpret_cast<float4*>(&g_AGGR[(size_t)n * DD + lane * 4]) = acc;
}

// ---------------------------------------------------------------------------
// Fused layer kernel (HMMA bf16 split-3x) — see R6; AGGR zeroing removed
// ---------------------------------------------------------------------------
__global__ void __launch_bounds__(256)
fused_mma_kernel(const float* __restrict__ xext,
                 const int* __restrict__ batch,
                 const float* __restrict__ b1,
                 const float* __restrict__ g1, const float* __restrict__ be1,
                 const float* __restrict__ mu1, const float* __restrict__ v1,
                 const float* __restrict__ b2,
                 const float* __restrict__ g2, const float* __restrict__ be2,
                 const float* __restrict__ mu2, const float* __restrict__ v2,
                 int layer) {
    extern __shared__ char smc[];
    const int tid = threadIdx.x;
    const int lane = tid & 31;
    const int wid = tid >> 5;
    const int wm = wid >> 1;
    const int wn = wid & 1;
    const int m0 = blockIdx.x * 128;
    const float* Ain = xext ? xext : g_X;

    float* s_sc1 = reinterpret_cast<float*>(smc + SM_SC1);
    float* s_sh1 = reinterpret_cast<float*>(smc + SM_SH1);
    float* s_sc2 = reinterpret_cast<float*>(smc + SM_SC2);
    float* s_sh2 = reinterpret_cast<float*>(smc + SM_SH2);

    const uint32_t aHi = smem_u32(smc + SM_AHI);
    const uint32_t aLo = smem_u32(smc + SM_ALO);
    const uint32_t wHi = smem_u32(smc + SM_WHI);
    const uint32_t wLo = smem_u32(smc + SM_WLO);

    if (tid < 128) {
        int c = tid;
        float s1 = g1[c] * rsqrtf(v1[c] + BN_EPS);
        s_sc1[c] = s1;
        s_sh1[c] = be1[c] + (b1[c] - mu1[c]) * s1;
        float s2 = g2[c] * rsqrtf(v2[c] + BN_EPS);
        s_sc2[c] = s2;
        s_sh2[c] = be2[c] + (b2[c] - mu2[c]) * s2;
    }
    {
        const int r = tid >> 1;
        const int h = tid & 1;
        const int m = m0 + r;
#pragma unroll
        for (int q = 0; q < 8; q++) {
            int c0 = h * 64 + q * 8;
            float4 v0 = make_float4(0.f, 0.f, 0.f, 0.f);
            float4 v1f = make_float4(0.f, 0.f, 0.f, 0.f);
            if (m < NN) {
                size_t gi = (size_t)m * DD + c0;
                v0 = *reinterpret_cast<const float4*>(&Ain[gi]);
                v1f = *reinterpret_cast<const float4*>(&Ain[gi + 4]);
                float4 a0 = *reinterpret_cast<const float4*>(&g_AGGR[gi]);
                float4 a1 = *reinterpret_cast<const float4*>(&g_AGGR[gi + 4]);
                v0.x += a0.x; v0.y += a0.y; v0.z += a0.z; v0.w += a0.w;
                v1f.x += a1.x; v1f.y += a1.y; v1f.z += a1.z; v1f.w += a1.w;
            }
            uint32_t off = sw_off(r, h * 8 + q);
            uint4 hi4 = make_uint4(pack_hi(v0.x, v0.y), pack_hi(v0.z, v0.w),
                                   pack_hi(v1f.x, v1f.y), pack_hi(v1f.z, v1f.w));
            uint4 lo4 = make_uint4(pack_lo(v0.x, v0.y), pack_lo(v0.z, v0.w),
                                   pack_lo(v1f.x, v1f.y), pack_lo(v1f.z, v1f.w));
            *reinterpret_cast<uint4*>(smc + SM_AHI + off) = hi4;
            *reinterpret_cast<uint4*>(smc + SM_ALO + off) = lo4;
        }
    }
    {
        const uint4* sh = reinterpret_cast<const uint4*>(g_WT[layer][0][0]);
        const uint4* sl = reinterpret_cast<const uint4*>(g_WT[layer][0][1]);
        uint4* dh = reinterpret_cast<uint4*>(smc + SM_WHI);
        uint4* dl = reinterpret_cast<uint4*>(smc + SM_WLO);
#pragma unroll
        for (int i = 0; i < 8; i++) {
            dh[tid + i * 256] = sh[tid + i * 256];
            dl[tid + i * 256] = sl[tid + i * 256];
        }
    }
    __syncthreads();

    const int lrow = lane & 15;
    const int lhalf = lane >> 4;
    const int ar0 = wm * 32 + lrow;
    const int ar1 = ar0 + 16;
    const int ar0b = ar0 * 256, ar0x = ar0 & 7;
    const int ar1b = ar1 * 256, ar1x = ar1 & 7;
    int brb[4], brx[4];
#pragma unroll
    for (int p = 0; p < 4; p++) {
        int nr = wn * 64 + p * 16 + lrow;
        brb[p] = nr * 256;
        brx[p] = nr & 7;
    }

    float acc[64];
#pragma unroll
    for (int i = 0; i < 64; i++) acc[i] = 0.f;

    for (int pass = 0; pass < 2; ++pass) {
#pragma unroll
        for (int ks = 0; ks < 8; ks++) {
            const int ch = ks * 2 + lhalf;
            uint32_t a0[4], a1[4];
            ldm_x4(a0, aHi + ar0b + ((uint32_t)(ch ^ ar0x) << 4));
            ldm_x4(a1, aHi + ar1b + ((uint32_t)(ch ^ ar1x) << 4));
            uint32_t bh[4][4], bl[4][4];
#pragma unroll
            for (int p = 0; p < 4; p++) {
                uint32_t o = (uint32_t)(ch ^ brx[p]) << 4;
                ldm_x4(bh[p], wHi + brb[p] + o);
                ldm_x4(bl[p], wLo + brb[p] + o);
            }
#pragma unroll
            for (int p = 0; p < 4; p++) {
                MMA_BF16(acc + (2 * p) * 4,      a0, bh[p][0], bh[p][2]);
                MMA_BF16(acc + (2 * p + 1) * 4,  a0, bh[p][1], bh[p][3]);
                MMA_BF16(acc + 32 + (2 * p) * 4,     a1, bh[p][0], bh[p][2]);
                MMA_BF16(acc + 32 + (2 * p + 1) * 4, a1, bh[p][1], bh[p][3]);
                MMA_BF16(acc + (2 * p) * 4,      a0, bl[p][0], bl[p][2]);
                MMA_BF16(acc + (2 * p + 1) * 4,  a0, bl[p][1], bl[p][3]);
                MMA_BF16(acc + 32 + (2 * p) * 4,     a1, bl[p][0], bl[p][2]);
                MMA_BF16(acc + 32 + (2 * p + 1) * 4, a1, bl[p][1], bl[p][3]);
            }
        }
#pragma unroll
        for (int ks = 0; ks < 8; ks++) {
            const int ch = ks * 2 + lhalf;
            uint32_t a0[4], a1[4];
            ldm_x4(a0, aLo + ar0b + ((uint32_t)(ch ^ ar0x) << 4));
            ldm_x4(a1, aLo + ar1b + ((uint32_t)(ch ^ ar1x) << 4));
            uint32_t bh[4][4];
#pragma unroll
            for (int p = 0; p < 4; p++)
                ldm_x4(bh[p], wHi + brb[p] + ((uint32_t)(ch ^ brx[p]) << 4));
#pragma unroll
            for (int p = 0; p < 4; p++) {
                MMA_BF16(acc + (2 * p) * 4,      a0, bh[p][0], bh[p][2]);
                MMA_BF16(acc + (2 * p + 1) * 4,  a0, bh[p][1], bh[p][3]);
                MMA_BF16(acc + 32 + (2 * p) * 4,     a1, bh[p][0], bh[p][2]);
                MMA_BF16(acc + 32 + (2 * p + 1) * 4, a1, bh[p][1], bh[p][3]);
            }
        }
        __syncthreads();

        if (pass == 0) {
#pragma unroll
            for (int mt = 0; mt < 2; mt++) {
                int rbase = wm * 32 + mt * 16 + (lane >> 2);
#pragma unroll
                for (int h = 0; h < 2; h++) {
                    int rr = rbase + 8 * h;
                    int rb = rr * 256, rx = rr & 7;
#pragma unroll
                    for (int nt = 0; nt < 8; nt++) {
                        int c = wn * 64 + nt * 8 + 2 * (lane & 3);
                        int ai = mt * 32 + nt * 4 + 2 * h;
                        float v0 = fmaxf(fmaf(acc[ai],     s_sc1[c],     s_sh1[c]),     0.f);
                        float v1f = fmaxf(fmaf(acc[ai + 1], s_sc1[c + 1], s_sh1[c + 1]), 0.f);
                        uint32_t off = (uint32_t)(rb + (((c >> 3) ^ rx) << 4) + ((c & 7) << 1));
                        *reinterpret_cast<uint32_t*>(smc + SM_AHI + off) = pack_hi(v0, v1f);
                        *reinterpret_cast<uint32_t*>(smc + SM_ALO + off) = pack_lo(v0, v1f);
                    }
                }
            }
            {
                const uint4* sh = reinterpret_cast<const uint4*>(g_WT[layer][1][0]);
                const uint4* sl = reinterpret_cast<const uint4*>(g_WT[layer][1][1]);
                uint4* dh = reinterpret_cast<uint4*>(smc + SM_WHI);
                uint4* dl = reinterpret_cast<uint4*>(smc + SM_WLO);
#pragma unroll
                for (int i = 0; i < 8; i++) {
                    dh[tid + i * 256] = sh[tid + i * 256];
                    dl[tid + i * 256] = sl[tid + i * 256];
                }
            }
#pragma unroll
            for (int i = 0; i < 64; i++) acc[i] = 0.f;
            __syncthreads();
        }
    }

    float* poolbase = &g_POOL[(size_t)(layer + 1) * GG * DD];
#pragma unroll
    for (int mt = 0; mt < 2; mt++) {
#pragma unroll
        for (int h = 0; h < 2; h++) {
            int m = m0 + wm * 32 + mt * 16 + (lane >> 2) + 8 * h;
            if (m < NN) {
                int g = batch[m];
#pragma unroll
                for (int nt = 0; nt < 8; nt++) {
                    int c = wn * 64 + nt * 8 + 2 * (lane & 3);
                    int ai = mt * 32 + nt * 4 + 2 * h;
                    float v0 = fmaxf(fmaf(acc[ai],     s_sc2[c],     s_sh2[c]),     0.f);
                    float v1f = fmaxf(fmaf(acc[ai + 1], s_sc2[c + 1], s_sh2[c + 1]), 0.f);
                    *reinterpret_cast<float2*>(&g_X[(size_t)m * DD + c]) = make_float2(v0, v1f);
                    red_add_v2(&poolbase[g * DD + c], v0, v1f);
                }
            }
        }
    }
}

// ---------------------------------------------------------------------------
__global__ void head_kernel(const float* __restrict__ fcw,
                            const float* __restrict__ fcb,
                            float* __restrict__ out) {
    __shared__ float s[OO * DD];
    const int g = blockIdx.x;
    const int d = threadIdx.x;
    const float inv = 1.0f / fmaxf(g_CNT[g], 1.0f);

    float acc[OO];
#pragma unroll
    for (int o = 0; o < OO; o++) acc[o] = 0.f;

    for (int i = 0; i < LYR + 1; i++) {
        float p = g_POOL[(size_t)i * GG * DD + g * DD + d] * inv;
        const float* wrow = &fcw[((size_t)i * DD + d) * OO];
#pragma unroll
        for (int o = 0; o < OO; o++) acc[o] = fmaf(p, wrow[o], acc[o]);
    }
#pragma unroll
    for (int o = 0; o < OO; o++) s[o * DD + d] = acc[o];

    for (int st = 64; st > 0; st >>= 1) {
        __syncthreads();
        if (d < st) {
#pragma unroll
            for (int o = 0; o < OO; o++) s[o * DD + d] += s[o * DD + d + st];
        }
    }
    __syncthreads();
    if (d < OO) {
        float b = 0.f;
        for (int i = 0; i < LYR + 1; i++) b += fcb[i * OO + d];
        out[g * OO + d] = s[d * DD] + b;
    }
}

// ---------------------------------------------------------------------------
extern "C" void kernel_launch(void* const* d_in, const int* in_sizes, int n_in,
                              void* d_out, int out_size) {
    const float* x     = (const float*)d_in[0];
    const int*   ei    = (const int*)d_in[1];
    const int*   eattr = (const int*)d_in[2];
    const int*   batch = (const int*)d_in[3];
    const float* bemb  = (const float*)d_in[4];
    const float* w1    = (const float*)d_in[5];
    const float* b1    = (const float*)d_in[6];
    const float* cbg   = (const float*)d_in[7];
    const float* cbb   = (const float*)d_in[8];
    const float* cbm   = (const float*)d_in[9];
    const float* cbv   = (const float*)d_in[10];
    const float* w2    = (const float*)d_in[11];
    const float* b2    = (const float*)d_in[12];
    const float* bg    = (const float*)d_in[13];
    const float* bb    = (const float*)d_in[14];
    const float* bm    = (const float*)d_in[15];
    const float* bv    = (const float*)d_in[16];
    const float* fcw   = (const float*)d_in[17];
    const float* fcb   = (const float*)d_in[18];
    float* out = (float*)d_out;

    const int gemm_grid = (NN + 127) / 128;           // 391
    const int pool_grid = (NN * 32 + 255) / 256;
    const int msg_grid = (NN + 7) / 8;                // warp per node, 8 warps/block

    cudaFuncSetAttribute(fused_mma_kernel,
                         cudaFuncAttributeMaxDynamicSharedMemorySize, SM_TOTAL);

    zero_pool_kernel<<<((LYR + 1) * GG * DD + 255) / 256, 256>>>();
    pool0_kernel<<<pool_grid, 256>>>(x, batch);
    hist_kernel<<<(EE + 255) / 256, 256>>>(ei);
    combo_kernel<<<dim3(512, LYR), 128>>>(bemb);
    prep_w_kernel<<<dim3(LYR, 2), 256>>>(w1, w2);
    scan_kernel<<<1, 1024>>>();
    scatter_kernel<<<(EE + 255) / 256, 256>>>(ei, eattr);

    for (int i = 0; i < LYR; i++) {
        const float* xin = (i == 0) ? x : nullptr;
        msg_csr_kernel<<<msg_grid, 256>>>(xin, i);
        fused_mma_kernel<<<gemm_grid, 256, SM_TOTAL>>>(
            xin, batch,
            b1 + i * DD, cbg + i * DD, cbb + i * DD, cbm + i * DD, cbv + i * DD,
            b2 + i * DD, bg + i * DD, bb + i * DD, bm + i * DD, bv + i * DD,
            i);
    }
    head_kernel<<<GG, DD>>>(fcw, fcb, out);
}